// round 11
// baseline (speedup 1.0000x reference)
#include <cuda_runtime.h>
#include <cuda_fp16.h>
#include <cstdint>

#define Bdim 8
#define Ndim 512
#define Sdim 4096
#define Hdim 1024

#define BM 128
#define BN 128
#define BK 64
#define STAGES 3
#define NKITER (Sdim / BK)          // 64
#define NTILES 256
#define NCTAS 296
#define NTHREADS 256

// conversion chunks: 1 chunk = 4 fp32 (16B) -> 4 fp16 (8B)
#define MAP_CH  524288               // per batch: 512*4096/4
#define DOC_CH  1048576              // per batch: 4096*1024/4
#define BATCH_CH (MAP_CH + DOC_CH)   // 1572864 (divisible by 64)
#define TOTAL_CH (Bdim * BATCH_CH)   // 12582912

#define A_ROW_B 144                  // 64 halves (128B) + 16B pad
#define B_ROW_B 272                  // 128 halves (256B) + 16B pad
#define A_STAGE_B (BM * A_ROW_B)     // 18432 B
#define B_STAGE_B (BK * B_ROW_B)     // 17408 B
#define STAGE_B   (A_STAGE_B + B_STAGE_B)   // 35840 B
#define DYN_SMEM  (STAGES * STAGE_B)        // 107520 B

// fp16 scratch + sync state (static device globals -- allowed scratch path)
__device__ __align__(16) __half g_doc_h[(size_t)Bdim * Sdim * Hdim];  // 67.1 MB
__device__ __align__(16) __half g_map_h[(size_t)Bdim * Ndim * Sdim];  // 33.6 MB
__device__ int g_prog[Bdim];
__device__ int g_flag[Bdim];
__device__ int g_tile;
__device__ int g_cvt;

__device__ __forceinline__ uint32_t smem_u32(const void* p) {
    uint32_t a;
    asm("{ .reg .u64 t; cvta.to.shared.u64 t, %1; cvt.u32.u64 %0, t; }" : "=r"(a) : "l"(p));
    return a;
}
__device__ __forceinline__ void cp16(uint32_t sdst, const void* gsrc) {
    asm volatile("cp.async.cg.shared.global [%0], [%1], 16;" :: "r"(sdst), "l"(gsrc));
}
__device__ __forceinline__ uint32_t h2u(__half2 h) {
    return *reinterpret_cast<uint32_t*>(&h);
}

// ---- conversion filler task (warp-collective, split issue/finish) ----
// All control decisions are broadcast from lane 0 -> warp-uniform.
__device__ __forceinline__ int conv_issue(const float* __restrict__ doc,
                                          const float* __restrict__ map,
                                          float4& v0, float4& v1, int lane) {
    int lo = 0;
    if (lane == 0) lo = atomicAdd(&g_cvt, 64);
    lo = __shfl_sync(0xffffffffu, lo, 0);
    if (lo >= TOTAL_CH) return -1;          // uniform (broadcast value)
    const int b = lo / BATCH_CH;
    const int r = lo - b * BATCH_CH;
    const float4* src;
    if (r < MAP_CH) src = (const float4*)map + (size_t)b * MAP_CH + r;
    else            src = (const float4*)doc + (size_t)b * DOC_CH + (r - MAP_CH);
    v0 = src[lane];
    v1 = src[lane + 32];
    return lo;
}
__device__ __forceinline__ void conv_finish(int lo, float4 v0, float4 v1, int lane) {
    const int b = lo / BATCH_CH;
    const int r = lo - b * BATCH_CH;
    uint2* dst;
    if (r < MAP_CH) dst = (uint2*)g_map_h + (size_t)b * MAP_CH + r;
    else            dst = (uint2*)g_doc_h + (size_t)b * DOC_CH + (r - MAP_CH);
    uint2 o0, o1;
    o0.x = h2u(__floats2half2_rn(v0.x, v0.y));
    o0.y = h2u(__floats2half2_rn(v0.z, v0.w));
    o1.x = h2u(__floats2half2_rn(v1.x, v1.y));
    o1.y = h2u(__floats2half2_rn(v1.z, v1.w));
    dst[lane] = o0;
    dst[lane + 32] = o1;
    __threadfence();
    __syncwarp();
    if (lane == 0) {
        const int old = atomicAdd(&g_prog[b], 64);
        if (old + 64 == BATCH_CH) atomicExch(&g_flag[b], 1);
    }
}
// warp-uniform flag read
__device__ __forceinline__ int flag_ready(int b, int lane) {
    int f = 0;
    if (lane == 0) f = atomicAdd(&g_flag[b], 0);
    return __shfl_sync(0xffffffffu, f, 0);
}

__global__ void reset_state() {
    if (threadIdx.x < Bdim) {
        g_prog[threadIdx.x] = 0;
        g_flag[threadIdx.x] = 0;
    }
    if (threadIdx.x == 0) { g_tile = 0; g_cvt = 0; }
    __threadfence();
}

__global__ void __launch_bounds__(NTHREADS, 2)
fused_pool(const float* __restrict__ doc,   // [B,S,H] fp32
           const float* __restrict__ map,   // [B,N,S] fp32
           const float* __restrict__ lens,  // [B,N]
           float* __restrict__ out)         // [B,N,H]
{
    extern __shared__ char smraw[];
    __shared__ int s_tile;
    __shared__ int s_done;               // conversion cursor exhausted (benign race)

    const int tid  = threadIdx.x;
    const int lane = tid & 31;
    const int w    = tid >> 5;
    const int wm   = w & 3;          // 4 warps along M (32 rows each)
    const int wn   = w >> 2;         // 2 warps along N (64 cols each)

    if (tid == 0) s_done = 0;

    const uint32_t sbase = smem_u32(smraw);

    const int t8 = lane >> 3;
    const int r8 = lane & 7;
    const uint32_t a_lane_off =
        (uint32_t)(((t8 & 1) * 8 + r8) * A_ROW_B + (t8 >> 1) * 16);
    const uint32_t b_lane_off =
        (uint32_t)(((t8 & 1) * 8 + r8) * B_ROW_B + (t8 >> 1) * 16);
    const int gid = lane >> 2, tq = lane & 3;

    for (;;) {
        if (tid == 0) s_tile = atomicAdd(&g_tile, 1);
        __syncthreads();   // broadcast tile; also fences smem reuse between tiles
        const int t = s_tile;
        if (t >= NTILES) break;

        const int b  = t >> 5;
        const int m0 = ((t >> 3) & 3) * BM;
        const int h0 = (t & 7) * BN;

        // spin-convert until this tile's batch is fully fp16 (warp-uniform)
        for (;;) {
            if (flag_ready(b, lane)) break;
            float4 v0, v1;
            const int lo = conv_issue(doc, map, v0, v1, lane);
            if (lo >= 0) conv_finish(lo, v0, v1, lane);
            else __nanosleep(512);
        }
        __threadfence();

        const __half* Ag = g_map_h + (size_t)b * Ndim * Sdim + (size_t)m0 * Sdim;
        const __half* Bg = g_doc_h + (size_t)b * Sdim * Hdim + h0;

        auto load_stage = [&](int st, int k0) {
            const uint32_t abase = sbase + (uint32_t)(st * STAGE_B);
            const uint32_t bbase = abase + A_STAGE_B;
            #pragma unroll
            for (int i = 0; i < 4; i++) {          // A: 1024 16B-chunks
                const int c = tid + NTHREADS * i;
                const int m = c >> 3, q = c & 7;
                cp16(abase + (uint32_t)(m * A_ROW_B + q * 16),
                     Ag + (size_t)m * Sdim + k0 + q * 8);
            }
            #pragma unroll
            for (int i = 0; i < 4; i++) {          // B: 1024 16B-chunks
                const int c = tid + NTHREADS * i;
                const int k = c >> 4, q = c & 15;
                cp16(bbase + (uint32_t)(k * B_ROW_B + q * 16),
                     Bg + (size_t)(k0 + k) * Hdim + q * 8);
            }
        };

        float acc[2][8][4];
        #pragma unroll
        for (int i = 0; i < 2; i++)
            #pragma unroll
            for (int j = 0; j < 8; j++)
                #pragma unroll
                for (int r = 0; r < 4; r++)
                    acc[i][j][r] = 0.0f;

        #pragma unroll
        for (int s = 0; s < STAGES - 1; s++) {
            load_stage(s, s * BK);
            asm volatile("cp.async.commit_group;");
        }

        #pragma unroll 1
        for (int kt = 0; kt < NKITER; kt++) {
            asm volatile("cp.async.wait_group 1;" ::: "memory");
            __syncthreads();

            // filler conversion: issue LDGs now, finish after the MMA block
            int clo = -1;
            float4 cv0, cv1;
            if (!s_done) {
                clo = conv_issue(doc, map, cv0, cv1, lane);
                if (clo < 0) s_done = 1;
            }

            const int st = kt % STAGES;
            const uint32_t abase = sbase + (uint32_t)(st * STAGE_B);
            const uint32_t awarp = abase + (uint32_t)((wm * 32) * A_ROW_B) + a_lane_off;
            const uint32_t bwarp = abase + A_STAGE_B + (uint32_t)((wn * 64) * 2) + b_lane_off;

            #pragma unroll
            for (int kc = 0; kc < 4; kc++) {       // four k=16 steps
                uint32_t a[2][4];
                #pragma unroll
                for (int i = 0; i < 2; i++) {
                    const uint32_t addr = awarp + (uint32_t)(i * 16 * A_ROW_B + kc * 32);
                    asm volatile(
                        "ldmatrix.sync.aligned.m8n8.x4.shared.b16 {%0,%1,%2,%3}, [%4];"
                        : "=r"(a[i][0]), "=r"(a[i][1]), "=r"(a[i][2]), "=r"(a[i][3])
                        : "r"(addr));
                }
                uint32_t bfr[8][2];
                #pragma unroll
                for (int jt = 0; jt < 4; jt++) {
                    const uint32_t addr = bwarp + (uint32_t)(kc * 16 * B_ROW_B + jt * 32);
                    asm volatile(
                        "ldmatrix.sync.aligned.m8n8.x4.trans.shared.b16 {%0,%1,%2,%3}, [%4];"
                        : "=r"(bfr[2 * jt][0]), "=r"(bfr[2 * jt][1]),
                          "=r"(bfr[2 * jt + 1][0]), "=r"(bfr[2 * jt + 1][1])
                        : "r"(addr));
                }
                #pragma unroll
                for (int i = 0; i < 2; i++)
                    #pragma unroll
                    for (int j = 0; j < 8; j++) {
                        asm volatile(
                            "mma.sync.aligned.m16n8k16.row.col.f32.f16.f16.f32 "
                            "{%0,%1,%2,%3}, {%4,%5,%6,%7}, {%8,%9}, {%0,%1,%2,%3};"
                            : "+f"(acc[i][j][0]), "+f"(acc[i][j][1]),
                              "+f"(acc[i][j][2]), "+f"(acc[i][j][3])
                            : "r"(a[i][0]), "r"(a[i][1]),
                              "r"(a[i][2]), "r"(a[i][3]),
                              "r"(bfr[j][0]), "r"(bfr[j][1]));
                    }
            }

            if (clo >= 0) conv_finish(clo, cv0, cv1, lane);

            const int ls = kt + STAGES - 1;
            if (ls < NKITER) load_stage(ls % STAGES, ls * BK);
            asm volatile("cp.async.commit_group;");
        }

        // epilogue: scale by 1/len, store float2 pairs
        const float* lb = lens + b * Ndim;
        #pragma unroll
        for (int i = 0; i < 2; i++) {
            const int r0 = m0 + wm * 32 + i * 16 + gid;
            const int r1 = r0 + 8;
            const float inv0 = 1.0f / lb[r0];
            const float inv1 = 1.0f / lb[r1];
            float* o0 = out + (size_t)b * Ndim * Hdim + (size_t)r0 * Hdim + h0;
            float* o1 = out + (size_t)b * Ndim * Hdim + (size_t)r1 * Hdim + h0;
            #pragma unroll
            for (int j = 0; j < 8; j++) {
                const int h = wn * 64 + j * 8 + 2 * tq;
                *reinterpret_cast<float2*>(o0 + h) =
                    make_float2(acc[i][j][0] * inv0, acc[i][j][1] * inv0);
                *reinterpret_cast<float2*>(o1 + h) =
                    make_float2(acc[i][j][2] * inv1, acc[i][j][3] * inv1);
            }
        }
    }

    // drain: no tile left -- convert until the cursor is exhausted (warp-uniform)
    for (;;) {
        float4 v0, v1;
        const int lo = conv_issue(doc, map, v0, v1, lane);
        if (lo < 0) break;
        conv_finish(lo, v0, v1, lane);
    }
}

extern "C" void kernel_launch(void* const* d_in, const int* in_sizes, int n_in,
                              void* d_out, int out_size) {
    const float* doc  = (const float*)d_in[0];   // [8, 4096, 1024]
    const float* map  = (const float*)d_in[1];   // [8, 512, 4096]
    const float* lens = (const float*)d_in[2];   // [8, 512]
    float* out = (float*)d_out;                  // [8, 512, 1024]

    cudaFuncSetAttribute(fused_pool, cudaFuncAttributeMaxDynamicSharedMemorySize, DYN_SMEM);

    reset_state<<<1, 32>>>();
    fused_pool<<<NCTAS, NTHREADS, DYN_SMEM>>>(doc, map, lens, out);
}

// round 12
// speedup vs baseline: 2.3948x; 2.3948x over previous
#include <cuda_runtime.h>
#include <cuda_fp16.h>
#include <cstdint>

#define Bdim 8
#define Ndim 512
#define Sdim 4096
#define Hdim 1024

#define BM 128
#define BN 128
#define BK 64
#define STAGES 3
#define NKITER (Sdim / BK)          // 64
#define NTHREADS 256

// fp16 SMEM tiles with padded rows (conflict-free ldmatrix groups)
#define A_ROW_B 144                  // 64 halves (128B) + 16B pad
#define B_ROW_B 272                  // 128 halves (256B) + 16B pad
#define A_STAGE_B (BM * A_ROW_B)     // 18432 B
#define B_STAGE_B (BK * B_ROW_B)     // 17408 B
#define STAGE_B   (A_STAGE_B + B_STAGE_B)   // 35840 B
#define DYN_SMEM  (STAGES * STAGE_B)        // 107520 B

// merged conversion: units of 8 floats (two float4 reads, one uint4 write)
#define DOC_N8 ((size_t)Bdim * Sdim * Hdim / 8)   // 4194304
#define MAP_N8 ((size_t)Bdim * Ndim * Sdim / 8)   // 2097152
#define TOT_N8 (DOC_N8 + MAP_N8)                   // 6291456
#define CVT_BLOCKS 3072
#define CVT_THREADS 256               // 786432 threads -> exactly 8 iters each

// fp16 scratch (static device globals -- allowed scratch path)
__device__ __align__(16) __half g_doc_h[(size_t)Bdim * Sdim * Hdim];  // 67.1 MB
__device__ __align__(16) __half g_map_h[(size_t)Bdim * Ndim * Sdim];  // 33.6 MB

__device__ __forceinline__ uint32_t smem_u32(const void* p) {
    uint32_t a;
    asm("{ .reg .u64 t; cvta.to.shared.u64 t, %1; cvt.u32.u64 %0, t; }" : "=r"(a) : "l"(p));
    return a;
}
__device__ __forceinline__ void cp16(uint32_t sdst, const void* gsrc) {
    asm volatile("cp.async.cg.shared.global [%0], [%1], 16;" :: "r"(sdst), "l"(gsrc));
}
__device__ __forceinline__ uint32_t h2u(__half2 h) {
    return *reinterpret_cast<uint32_t*>(&h);
}

// ---------------- merged conversion pre-pass (doc + map in one kernel) ----------------
__global__ void __launch_bounds__(CVT_THREADS)
cvt_all(const float* __restrict__ doc, const float* __restrict__ map) {
    size_t i = (size_t)blockIdx.x * blockDim.x + threadIdx.x;
    const size_t stride = (size_t)gridDim.x * blockDim.x;
    for (; i < TOT_N8; i += stride) {
        const float4* s4;
        uint4* d4;
        if (i < DOC_N8) {
            s4 = (const float4*)doc + 2 * i;
            d4 = (uint4*)g_doc_h + i;
        } else {
            const size_t j = i - DOC_N8;
            s4 = (const float4*)map + 2 * j;
            d4 = (uint4*)g_map_h + j;
        }
        const float4 v0 = s4[0];
        const float4 v1 = s4[1];
        uint4 o;
        o.x = h2u(__floats2half2_rn(v0.x, v0.y));
        o.y = h2u(__floats2half2_rn(v0.z, v0.w));
        o.z = h2u(__floats2half2_rn(v1.x, v1.y));
        o.w = h2u(__floats2half2_rn(v1.z, v1.w));
        *d4 = o;
    }
}

// ---------------- main GEMM (identical to the 150.5us R6 kernel) ----------------
__global__ void __launch_bounds__(NTHREADS, 2)
mean_pool_mma(const float* __restrict__ lens,  // [B,N]
              float* __restrict__ out)         // [B,N,H]
{
    extern __shared__ char smraw[];

    const int tid  = threadIdx.x;
    const int lane = tid & 31;
    const int w    = tid >> 5;       // 8 warps
    const int wm   = w & 3;          // 4 warps along M (32 rows each)
    const int wn   = w >> 2;         // 2 warps along N (64 cols each)

    const int b  = blockIdx.z;
    const int m0 = blockIdx.y * BM;
    const int h0 = blockIdx.x * BN;

    const __half* Ag = g_map_h + (size_t)b * Ndim * Sdim + (size_t)m0 * Sdim;  // [BM, S]
    const __half* Bg = g_doc_h + (size_t)b * Sdim * Hdim + h0;                 // [S, BN]

    const uint32_t sbase = smem_u32(smraw);

    auto load_stage = [&](int st, int k0) {
        const uint32_t abase = sbase + (uint32_t)(st * STAGE_B);
        const uint32_t bbase = abase + A_STAGE_B;
        #pragma unroll
        for (int i = 0; i < 4; i++) {          // A: 1024 16B-chunks
            const int c = tid + NTHREADS * i;
            const int m = c >> 3, q = c & 7;
            cp16(abase + (uint32_t)(m * A_ROW_B + q * 16),
                 Ag + (size_t)m * Sdim + k0 + q * 8);
        }
        #pragma unroll
        for (int i = 0; i < 4; i++) {          // B: 1024 16B-chunks
            const int c = tid + NTHREADS * i;
            const int k = c >> 4, q = c & 15;
            cp16(bbase + (uint32_t)(k * B_ROW_B + q * 16),
                 Bg + (size_t)(k0 + k) * Hdim + q * 8);
        }
    };

    float acc[2][8][4];
    #pragma unroll
    for (int i = 0; i < 2; i++)
        #pragma unroll
        for (int j = 0; j < 8; j++)
            #pragma unroll
            for (int r = 0; r < 4; r++)
                acc[i][j][r] = 0.0f;

    #pragma unroll
    for (int s = 0; s < STAGES - 1; s++) {
        load_stage(s, s * BK);
        asm volatile("cp.async.commit_group;");
    }

    const int t8 = lane >> 3;
    const int r8 = lane & 7;
    const uint32_t a_lane_off =
        (uint32_t)(((t8 & 1) * 8 + r8) * A_ROW_B + (t8 >> 1) * 16);
    const uint32_t b_lane_off =
        (uint32_t)(((t8 & 1) * 8 + r8) * B_ROW_B + (t8 >> 1) * 16);

    #pragma unroll 1
    for (int kt = 0; kt < NKITER; kt++) {
        asm volatile("cp.async.wait_group 1;" ::: "memory");
        __syncthreads();

        const int st = kt % STAGES;
        const uint32_t abase = sbase + (uint32_t)(st * STAGE_B);
        const uint32_t awarp = abase + (uint32_t)((wm * 32) * A_ROW_B) + a_lane_off;
        const uint32_t bwarp = abase + A_STAGE_B + (uint32_t)((wn * 64) * 2) + b_lane_off;

        #pragma unroll
        for (int kc = 0; kc < 4; kc++) {       // four k=16 steps
            uint32_t a[2][4];
            #pragma unroll
            for (int i = 0; i < 2; i++) {
                const uint32_t addr = awarp + (uint32_t)(i * 16 * A_ROW_B + kc * 32);
                asm volatile(
                    "ldmatrix.sync.aligned.m8n8.x4.shared.b16 {%0,%1,%2,%3}, [%4];"
                    : "=r"(a[i][0]), "=r"(a[i][1]), "=r"(a[i][2]), "=r"(a[i][3])
                    : "r"(addr));
            }
            uint32_t bfr[8][2];
            #pragma unroll
            for (int jt = 0; jt < 4; jt++) {
                const uint32_t addr = bwarp + (uint32_t)(kc * 16 * B_ROW_B + jt * 32);
                asm volatile(
                    "ldmatrix.sync.aligned.m8n8.x4.trans.shared.b16 {%0,%1,%2,%3}, [%4];"
                    : "=r"(bfr[2 * jt][0]), "=r"(bfr[2 * jt][1]),
                      "=r"(bfr[2 * jt + 1][0]), "=r"(bfr[2 * jt + 1][1])
                    : "r"(addr));
            }
            #pragma unroll
            for (int i = 0; i < 2; i++)
                #pragma unroll
                for (int j = 0; j < 8; j++) {
                    asm volatile(
                        "mma.sync.aligned.m16n8k16.row.col.f32.f16.f16.f32 "
                        "{%0,%1,%2,%3}, {%4,%5,%6,%7}, {%8,%9}, {%0,%1,%2,%3};"
                        : "+f"(acc[i][j][0]), "+f"(acc[i][j][1]),
                          "+f"(acc[i][j][2]), "+f"(acc[i][j][3])
                        : "r"(a[i][0]), "r"(a[i][1]),
                          "r"(a[i][2]), "r"(a[i][3]),
                          "r"(bfr[j][0]), "r"(bfr[j][1]));
                }
        }

        const int ls = kt + STAGES - 1;
        if (ls < NKITER) load_stage(ls % STAGES, ls * BK);
        asm volatile("cp.async.commit_group;");
    }

    // epilogue: scale by 1/len, store float2 pairs
    const float* lb = lens + b * Ndim;
    const int gid = lane >> 2, tq = lane & 3;
    #pragma unroll
    for (int i = 0; i < 2; i++) {
        const int r0 = m0 + wm * 32 + i * 16 + gid;
        const int r1 = r0 + 8;
        const float inv0 = 1.0f / lb[r0];
        const float inv1 = 1.0f / lb[r1];
        float* o0 = out + (size_t)b * Ndim * Hdim + (size_t)r0 * Hdim + h0;
        float* o1 = out + (size_t)b * Ndim * Hdim + (size_t)r1 * Hdim + h0;
        #pragma unroll
        for (int j = 0; j < 8; j++) {
            const int h = wn * 64 + j * 8 + 2 * tq;
            *reinterpret_cast<float2*>(o0 + h) =
                make_float2(acc[i][j][0] * inv0, acc[i][j][1] * inv0);
            *reinterpret_cast<float2*>(o1 + h) =
                make_float2(acc[i][j][2] * inv1, acc[i][j][3] * inv1);
        }
    }
}

extern "C" void kernel_launch(void* const* d_in, const int* in_sizes, int n_in,
                              void* d_out, int out_size) {
    const float* doc  = (const float*)d_in[0];   // [8, 4096, 1024]
    const float* map  = (const float*)d_in[1];   // [8, 512, 4096]
    const float* lens = (const float*)d_in[2];   // [8, 512]
    float* out = (float*)d_out;                  // [8, 512, 1024]

    cvt_all<<<CVT_BLOCKS, CVT_THREADS>>>(doc, map);

    cudaFuncSetAttribute(mean_pool_mma, cudaFuncAttributeMaxDynamicSharedMemorySize, DYN_SMEM);
    dim3 grid(Hdim / BN, Ndim / BM, Bdim);   // (8, 4, 8) = 256 CTAs
    mean_pool_mma<<<grid, NTHREADS, DYN_SMEM>>>(lens, out);
}

// round 13
// speedup vs baseline: 2.5376x; 1.0597x over previous
#include <cuda_runtime.h>
#include <cuda_fp16.h>
#include <cstdint>

#define Bdim 8
#define Ndim 512
#define Sdim 4096
#define Hdim 1024

#define BM 128
#define BN 128
#define BK 64
#define STAGES 3
#define NKITER (Sdim / BK)          // 64
#define NTHREADS 256

#define A_ROW_B 144                  // 64 halves (128B) + 16B pad
#define B_ROW_B 272                  // 128 halves (256B) + 16B pad
#define A_STAGE_B (BM * A_ROW_B)     // 18432 B
#define B_STAGE_B (BK * B_ROW_B)     // 17408 B
#define STAGE_B   (A_STAGE_B + B_STAGE_B)   // 35840 B
#define DYN_SMEM  (STAGES * STAGE_B)        // 107520 B

// merged conversion: units of 8 floats
#define DOC_N8 ((size_t)Bdim * Sdim * Hdim / 8)   // 4194304
#define MAP_N8 ((size_t)Bdim * Ndim * Sdim / 8)   // 2097152
#define TOT_N8 (DOC_N8 + MAP_N8)                   // 6291456
#define CVT_BLOCKS 3072
#define CVT_THREADS 256

__device__ __align__(16) __half g_doc_h[(size_t)Bdim * Sdim * Hdim];  // 67.1 MB
__device__ __align__(16) __half g_map_h[(size_t)Bdim * Ndim * Sdim];  // 33.6 MB

__device__ __forceinline__ uint32_t smem_u32(const void* p) {
    uint32_t a;
    asm("{ .reg .u64 t; cvta.to.shared.u64 t, %1; cvt.u32.u64 %0, t; }" : "=r"(a) : "l"(p));
    return a;
}
__device__ __forceinline__ void cp16(uint32_t sdst, const void* gsrc) {
    asm volatile("cp.async.cg.shared.global [%0], [%1], 16;" :: "r"(sdst), "l"(gsrc));
}
__device__ __forceinline__ uint32_t h2u(__half2 h) {
    return *reinterpret_cast<uint32_t*>(&h);
}
__device__ __forceinline__ void mbar_init(uint32_t bar, uint32_t cnt) {
    asm volatile("mbarrier.init.shared.b64 [%0], %1;" :: "r"(bar), "r"(cnt) : "memory");
}
__device__ __forceinline__ void mbar_wait(uint32_t bar, uint32_t parity) {
    asm volatile(
        "{\n\t.reg .pred P1;\n\t"
        "WL_%=:\n\t"
        "mbarrier.try_wait.parity.shared.b64 P1, [%0], %1, 0x989680;\n\t"
        "@P1 bra.uni WD_%=;\n\t"
        "bra.uni WL_%=;\n\t"
        "WD_%=:\n\t}"
        :: "r"(bar), "r"(parity) : "memory");
}
__device__ __forceinline__ void mbar_arrive(uint32_t bar) {
    asm volatile("mbarrier.arrive.shared.b64 _, [%0];" :: "r"(bar) : "memory");
}
__device__ __forceinline__ void cp_async_arrive(uint32_t bar) {
    asm volatile("cp.async.mbarrier.arrive.noinc.shared.b64 [%0];" :: "r"(bar) : "memory");
}

// ---------------- merged conversion pre-pass (unchanged, at HBM cap) ----------------
__global__ void __launch_bounds__(CVT_THREADS)
cvt_all(const float* __restrict__ doc, const float* __restrict__ map) {
    size_t i = (size_t)blockIdx.x * blockDim.x + threadIdx.x;
    const size_t stride = (size_t)gridDim.x * blockDim.x;
    for (; i < TOT_N8; i += stride) {
        const float4* s4;
        uint4* d4;
        if (i < DOC_N8) {
            s4 = (const float4*)doc + 2 * i;
            d4 = (uint4*)g_doc_h + i;
        } else {
            const size_t j = i - DOC_N8;
            s4 = (const float4*)map + 2 * j;
            d4 = (uint4*)g_map_h + j;
        }
        const float4 v0 = s4[0];
        const float4 v1 = s4[1];
        uint4 o;
        o.x = h2u(__floats2half2_rn(v0.x, v0.y));
        o.y = h2u(__floats2half2_rn(v0.z, v0.w));
        o.z = h2u(__floats2half2_rn(v1.x, v1.y));
        o.w = h2u(__floats2half2_rn(v1.z, v1.w));
        *d4 = o;
    }
}

// ---------------- main GEMM: per-warp mbarrier pipeline, no bar.sync in mainloop ----------------
__global__ void __launch_bounds__(NTHREADS, 2)
mean_pool_mma(const float* __restrict__ lens,  // [B,N]
              float* __restrict__ out)         // [B,N,H]
{
    extern __shared__ char smraw[];
    __shared__ __align__(8) uint64_t full_bar[STAGES];
    __shared__ __align__(8) uint64_t empty_bar[STAGES];

    const int tid  = threadIdx.x;
    const int lane = tid & 31;
    const int w    = tid >> 5;       // 8 warps
    const int wm   = w & 3;          // 4 warps along M (32 rows each)
    const int wn   = w >> 2;         // 2 warps along N (64 cols each)

    const int b  = blockIdx.z;
    const int m0 = blockIdx.y * BM;
    const int h0 = blockIdx.x * BN;

    const __half* Ag = g_map_h + (size_t)b * Ndim * Sdim + (size_t)m0 * Sdim;  // [BM, S]
    const __half* Bg = g_doc_h + (size_t)b * Sdim * Hdim + h0;                 // [S, BN]

    const uint32_t sbase = smem_u32(smraw);
    uint32_t fbar[STAGES], ebar[STAGES];
    #pragma unroll
    for (int s = 0; s < STAGES; s++) {
        fbar[s] = smem_u32(&full_bar[s]);
        ebar[s] = smem_u32(&empty_bar[s]);
    }

    if (tid == 0) {
        #pragma unroll
        for (int s = 0; s < STAGES; s++) {
            mbar_init(fbar[s], NTHREADS);   // full: all 256 threads' cp.asyncs complete
            mbar_init(ebar[s], 8);          // empty: 8 warps done reading
        }
    }
    __syncthreads();

    // parity bits per stage (bit s): full starts 0 (consumer), empty starts 1 (producer idiom)
    int phf = 0;
    int phe = (1 << STAGES) - 1;

    // producer: wait stage-empty, issue this thread's 8 chunks, async-arrive on full
    auto fill_stage = [&](int st, int k0) {
        mbar_wait(ebar[st], (phe >> st) & 1);
        phe ^= (1 << st);
        const uint32_t abase = sbase + (uint32_t)(st * STAGE_B);
        const uint32_t bbase = abase + A_STAGE_B;
        #pragma unroll
        for (int i = 0; i < 4; i++) {          // A: 1024 16B-chunks
            const int c = tid + NTHREADS * i;
            const int m = c >> 3, q = c & 7;
            cp16(abase + (uint32_t)(m * A_ROW_B + q * 16),
                 Ag + (size_t)m * Sdim + k0 + q * 8);
        }
        #pragma unroll
        for (int i = 0; i < 4; i++) {          // B: 1024 16B-chunks
            const int c = tid + NTHREADS * i;
            const int k = c >> 4, q = c & 15;
            cp16(bbase + (uint32_t)(k * B_ROW_B + q * 16),
                 Bg + (size_t)(k0 + k) * Hdim + q * 8);
        }
        cp_async_arrive(fbar[st]);
    };

    float acc[2][8][4];
    #pragma unroll
    for (int i = 0; i < 2; i++)
        #pragma unroll
        for (int j = 0; j < 8; j++)
            #pragma unroll
            for (int r = 0; r < 4; r++)
                acc[i][j][r] = 0.0f;

    // prologue: fill stages 0,1 (empty-waits pass immediately via flipped parity)
    fill_stage(0, 0);
    fill_stage(1, BK);

    const int t8 = lane >> 3;
    const int r8 = lane & 7;
    const uint32_t a_lane_off =
        (uint32_t)(((t8 & 1) * 8 + r8) * A_ROW_B + (t8 >> 1) * 16);
    const uint32_t b_lane_off =
        (uint32_t)(((t8 & 1) * 8 + r8) * B_ROW_B + (t8 >> 1) * 16);

    int st = 0;
    #pragma unroll 1
    for (int kt = 0; kt < NKITER; kt++) {
        // consume: wait stage full
        mbar_wait(fbar[st], (phf >> st) & 1);
        phf ^= (1 << st);

        const uint32_t abase = sbase + (uint32_t)(st * STAGE_B);
        const uint32_t awarp = abase + (uint32_t)((wm * 32) * A_ROW_B) + a_lane_off;
        const uint32_t bwarp = abase + A_STAGE_B + (uint32_t)((wn * 64) * 2) + b_lane_off;

        #pragma unroll
        for (int kc = 0; kc < 4; kc++) {       // four k=16 steps
            uint32_t a[2][4];
            #pragma unroll
            for (int i = 0; i < 2; i++) {
                const uint32_t addr = awarp + (uint32_t)(i * 16 * A_ROW_B + kc * 32);
                asm volatile(
                    "ldmatrix.sync.aligned.m8n8.x4.shared.b16 {%0,%1,%2,%3}, [%4];"
                    : "=r"(a[i][0]), "=r"(a[i][1]), "=r"(a[i][2]), "=r"(a[i][3])
                    : "r"(addr));
            }
            uint32_t bfr[8][2];
            #pragma unroll
            for (int jt = 0; jt < 4; jt++) {
                const uint32_t addr = bwarp + (uint32_t)(kc * 16 * B_ROW_B + jt * 32);
                asm volatile(
                    "ldmatrix.sync.aligned.m8n8.x4.trans.shared.b16 {%0,%1,%2,%3}, [%4];"
                    : "=r"(bfr[2 * jt][0]), "=r"(bfr[2 * jt][1]),
                      "=r"(bfr[2 * jt + 1][0]), "=r"(bfr[2 * jt + 1][1])
                    : "r"(addr));
            }
            #pragma unroll
            for (int i = 0; i < 2; i++)
                #pragma unroll
                for (int j = 0; j < 8; j++) {
                    asm volatile(
                        "mma.sync.aligned.m16n8k16.row.col.f32.f16.f16.f32 "
                        "{%0,%1,%2,%3}, {%4,%5,%6,%7}, {%8,%9}, {%0,%1,%2,%3};"
                        : "+f"(acc[i][j][0]), "+f"(acc[i][j][1]),
                          "+f"(acc[i][j][2]), "+f"(acc[i][j][3])
                        : "r"(a[i][0]), "r"(a[i][1]),
                          "r"(a[i][2]), "r"(a[i][3]),
                          "r"(bfr[j][0]), "r"(bfr[j][1]));
                }
        }

        // this warp is done reading stage st (ldmatrix are in-order, warp-synchronous)
        if (lane == 0) mbar_arrive(ebar[st]);

        const int ls = kt + STAGES - 1;
        if (ls < NKITER) {
            int s2 = st + STAGES - 1;
            if (s2 >= STAGES) s2 -= STAGES;    // (kt+2) % 3
            fill_stage(s2, ls * BK);
        }

        if (++st == STAGES) st = 0;
    }

    // epilogue: scale by 1/len, store float2 pairs
    const float* lb = lens + b * Ndim;
    const int gid = lane >> 2, tq = lane & 3;
    #pragma unroll
    for (int i = 0; i < 2; i++) {
        const int r0 = m0 + wm * 32 + i * 16 + gid;
        const int r1 = r0 + 8;
        const float inv0 = 1.0f / lb[r0];
        const float inv1 = 1.0f / lb[r1];
        float* o0 = out + (size_t)b * Ndim * Hdim + (size_t)r0 * Hdim + h0;
        float* o1 = out + (size_t)b * Ndim * Hdim + (size_t)r1 * Hdim + h0;
        #pragma unroll
        for (int j = 0; j < 8; j++) {
            const int h = wn * 64 + j * 8 + 2 * tq;
            *reinterpret_cast<float2*>(o0 + h) =
                make_float2(acc[i][j][0] * inv0, acc[i][j][1] * inv0);
            *reinterpret_cast<float2*>(o1 + h) =
                make_float2(acc[i][j][2] * inv1, acc[i][j][3] * inv1);
        }
    }
}

extern "C" void kernel_launch(void* const* d_in, const int* in_sizes, int n_in,
                              void* d_out, int out_size) {
    const float* doc  = (const float*)d_in[0];   // [8, 4096, 1024]
    const float* map  = (const float*)d_in[1];   // [8, 512, 4096]
    const float* lens = (const float*)d_in[2];   // [8, 512]
    float* out = (float*)d_out;                  // [8, 512, 1024]

    cvt_all<<<CVT_BLOCKS, CVT_THREADS>>>(doc, map);

    cudaFuncSetAttribute(mean_pool_mma, cudaFuncAttributeMaxDynamicSharedMemorySize, DYN_SMEM);
    dim3 grid(Hdim / BN, Ndim / BM, Bdim);   // (8, 4, 8) = 256 CTAs
    mean_pool_mma<<<grid, NTHREADS, DYN_SMEM>>>(lens, out);
}

// round 14
// speedup vs baseline: 2.5688x; 1.0123x over previous
#include <cuda_runtime.h>
#include <cuda_fp16.h>
#include <cstdint>

#define Bdim 8
#define Ndim 512
#define Sdim 4096
#define Hdim 1024

#define BM 128
#define BN 128
#define BK 64
#define STAGES 3
#define NKITER (Sdim / BK)          // 64
#define NTHREADS 128
#define NWARPS 4

#define A_ROW_B 144                  // 64 halves (128B) + 16B pad
#define B_ROW_B 272                  // 128 halves (256B) + 16B pad
#define A_STAGE_B (BM * A_ROW_B)     // 18432 B
#define B_STAGE_B (BK * B_ROW_B)     // 17408 B
#define STAGE_B   (A_STAGE_B + B_STAGE_B)   // 35840 B
#define DYN_SMEM  (STAGES * STAGE_B)        // 107520 B

// merged conversion: units of 8 floats
#define DOC_N8 ((size_t)Bdim * Sdim * Hdim / 8)   // 4194304
#define MAP_N8 ((size_t)Bdim * Ndim * Sdim / 8)   // 2097152
#define TOT_N8 (DOC_N8 + MAP_N8)                   // 6291456
#define CVT_BLOCKS 3072
#define CVT_THREADS 256

__device__ __align__(16) __half g_doc_h[(size_t)Bdim * Sdim * Hdim];  // 67.1 MB
__device__ __align__(16) __half g_map_h[(size_t)Bdim * Ndim * Sdim];  // 33.6 MB

__device__ __forceinline__ uint32_t smem_u32(const void* p) {
    uint32_t a;
    asm("{ .reg .u64 t; cvta.to.shared.u64 t, %1; cvt.u32.u64 %0, t; }" : "=r"(a) : "l"(p));
    return a;
}
__device__ __forceinline__ void cp16(uint32_t sdst, const void* gsrc) {
    asm volatile("cp.async.cg.shared.global [%0], [%1], 16;" :: "r"(sdst), "l"(gsrc));
}
__device__ __forceinline__ uint32_t h2u(__half2 h) {
    return *reinterpret_cast<uint32_t*>(&h);
}
__device__ __forceinline__ void mbar_init(uint32_t bar, uint32_t cnt) {
    asm volatile("mbarrier.init.shared.b64 [%0], %1;" :: "r"(bar), "r"(cnt) : "memory");
}
__device__ __forceinline__ void mbar_wait(uint32_t bar, uint32_t parity) {
    asm volatile(
        "{\n\t.reg .pred P1;\n\t"
        "WL_%=:\n\t"
        "mbarrier.try_wait.parity.shared.b64 P1, [%0], %1, 0x989680;\n\t"
        "@P1 bra.uni WD_%=;\n\t"
        "bra.uni WL_%=;\n\t"
        "WD_%=:\n\t}"
        :: "r"(bar), "r"(parity) : "memory");
}
__device__ __forceinline__ void mbar_arrive(uint32_t bar) {
    asm volatile("mbarrier.arrive.shared.b64 _, [%0];" :: "r"(bar) : "memory");
}
__device__ __forceinline__ void cp_async_arrive(uint32_t bar) {
    asm volatile("cp.async.mbarrier.arrive.noinc.shared.b64 [%0];" :: "r"(bar) : "memory");
}

// ---------------- merged conversion pre-pass (unchanged, at HBM cap) ----------------
__global__ void __launch_bounds__(CVT_THREADS)
cvt_all(const float* __restrict__ doc, const float* __restrict__ map) {
    size_t i = (size_t)blockIdx.x * blockDim.x + threadIdx.x;
    const size_t stride = (size_t)gridDim.x * blockDim.x;
    for (; i < TOT_N8; i += stride) {
        const float4* s4;
        uint4* d4;
        if (i < DOC_N8) {
            s4 = (const float4*)doc + 2 * i;
            d4 = (uint4*)g_doc_h + i;
        } else {
            const size_t j = i - DOC_N8;
            s4 = (const float4*)map + 2 * j;
            d4 = (uint4*)g_map_h + j;
        }
        const float4 v0 = s4[0];
        const float4 v1 = s4[1];
        uint4 o;
        o.x = h2u(__floats2half2_rn(v0.x, v0.y));
        o.y = h2u(__floats2half2_rn(v0.z, v0.w));
        o.z = h2u(__floats2half2_rn(v1.x, v1.y));
        o.w = h2u(__floats2half2_rn(v1.z, v1.w));
        *d4 = o;
    }
}

// ---------------- main GEMM: mbarrier pipeline + 64x64 warp tiles ----------------
__global__ void __launch_bounds__(NTHREADS, 2)
mean_pool_mma(const float* __restrict__ lens,  // [B,N]
              float* __restrict__ out)         // [B,N,H]
{
    extern __shared__ char smraw[];
    __shared__ __align__(8) uint64_t full_bar[STAGES];
    __shared__ __align__(8) uint64_t empty_bar[STAGES];

    const int tid  = threadIdx.x;
    const int lane = tid & 31;
    const int w    = tid >> 5;       // 4 warps
    const int wm   = w & 1;          // 2 warps along M (64 rows each)
    const int wn   = w >> 1;         // 2 warps along N (64 cols each)

    const int b  = blockIdx.z;
    const int m0 = blockIdx.y * BM;
    const int h0 = blockIdx.x * BN;

    const __half* Ag = g_map_h + (size_t)b * Ndim * Sdim + (size_t)m0 * Sdim;  // [BM, S]
    const __half* Bg = g_doc_h + (size_t)b * Sdim * Hdim + h0;                 // [S, BN]

    const uint32_t sbase = smem_u32(smraw);
    uint32_t fbar[STAGES], ebar[STAGES];
    #pragma unroll
    for (int s = 0; s < STAGES; s++) {
        fbar[s] = smem_u32(&full_bar[s]);
        ebar[s] = smem_u32(&empty_bar[s]);
    }

    if (tid == 0) {
        #pragma unroll
        for (int s = 0; s < STAGES; s++) {
            mbar_init(fbar[s], NTHREADS);   // full: all 128 threads' cp.asyncs complete
            mbar_init(ebar[s], NWARPS);     // empty: 4 warps done reading
        }
    }
    __syncthreads();

    int phf = 0;
    int phe = (1 << STAGES) - 1;

    auto fill_stage = [&](int st, int k0) {
        mbar_wait(ebar[st], (phe >> st) & 1);
        phe ^= (1 << st);
        const uint32_t abase = sbase + (uint32_t)(st * STAGE_B);
        const uint32_t bbase = abase + A_STAGE_B;
        #pragma unroll
        for (int i = 0; i < 8; i++) {          // A: 1024 16B-chunks
            const int c = tid + NTHREADS * i;
            const int m = c >> 3, q = c & 7;
            cp16(abase + (uint32_t)(m * A_ROW_B + q * 16),
                 Ag + (size_t)m * Sdim + k0 + q * 8);
        }
        #pragma unroll
        for (int i = 0; i < 8; i++) {          // B: 1024 16B-chunks
            const int c = tid + NTHREADS * i;
            const int k = c >> 4, q = c & 15;
            cp16(bbase + (uint32_t)(k * B_ROW_B + q * 16),
                 Bg + (size_t)(k0 + k) * Hdim + q * 8);
        }
        cp_async_arrive(fbar[st]);
    };

    float acc[4][8][4];
    #pragma unroll
    for (int i = 0; i < 4; i++)
        #pragma unroll
        for (int j = 0; j < 8; j++)
            #pragma unroll
            for (int r = 0; r < 4; r++)
                acc[i][j][r] = 0.0f;

    // prologue: fill stages 0,1
    fill_stage(0, 0);
    fill_stage(1, BK);

    const int t8 = lane >> 3;
    const int r8 = lane & 7;
    const uint32_t a_lane_off =
        (uint32_t)(((t8 & 1) * 8 + r8) * A_ROW_B + (t8 >> 1) * 16);
    const uint32_t b_lane_off =
        (uint32_t)(((t8 & 1) * 8 + r8) * B_ROW_B + (t8 >> 1) * 16);

    int st = 0;
    #pragma unroll 1
    for (int kt = 0; kt < NKITER; kt++) {
        mbar_wait(fbar[st], (phf >> st) & 1);
        phf ^= (1 << st);

        const uint32_t abase = sbase + (uint32_t)(st * STAGE_B);
        const uint32_t awarp = abase + (uint32_t)((wm * 64) * A_ROW_B) + a_lane_off;
        const uint32_t bwarp = abase + A_STAGE_B + (uint32_t)((wn * 64) * 2) + b_lane_off;

        #pragma unroll
        for (int kc = 0; kc < 4; kc++) {       // four k=16 steps
            uint32_t a[4][4];
            #pragma unroll
            for (int i = 0; i < 4; i++) {      // 4 m16 tiles
                const uint32_t addr = awarp + (uint32_t)(i * 16 * A_ROW_B + kc * 32);
                asm volatile(
                    "ldmatrix.sync.aligned.m8n8.x4.shared.b16 {%0,%1,%2,%3}, [%4];"
                    : "=r"(a[i][0]), "=r"(a[i][1]), "=r"(a[i][2]), "=r"(a[i][3])
                    : "r"(addr));
            }
            uint32_t bfr[8][2];
            #pragma unroll
            for (int jt = 0; jt < 4; jt++) {   // 8 n8 tiles
                const uint32_t addr = bwarp + (uint32_t)(kc * 16 * B_ROW_B + jt * 32);
                asm volatile(
                    "ldmatrix.sync.aligned.m8n8.x4.trans.shared.b16 {%0,%1,%2,%3}, [%4];"
                    : "=r"(bfr[2 * jt][0]), "=r"(bfr[2 * jt][1]),
                      "=r"(bfr[2 * jt + 1][0]), "=r"(bfr[2 * jt + 1][1])
                    : "r"(addr));
            }
            #pragma unroll
            for (int i = 0; i < 4; i++)
                #pragma unroll
                for (int j = 0; j < 8; j++) {
                    asm volatile(
                        "mma.sync.aligned.m16n8k16.row.col.f32.f16.f16.f32 "
                        "{%0,%1,%2,%3}, {%4,%5,%6,%7}, {%8,%9}, {%0,%1,%2,%3};"
                        : "+f"(acc[i][j][0]), "+f"(acc[i][j][1]),
                          "+f"(acc[i][j][2]), "+f"(acc[i][j][3])
                        : "r"(a[i][0]), "r"(a[i][1]),
                          "r"(a[i][2]), "r"(a[i][3]),
                          "r"(bfr[j][0]), "r"(bfr[j][1]));
                }
        }

        if (lane == 0) mbar_arrive(ebar[st]);

        const int ls = kt + STAGES - 1;
        if (ls < NKITER) {
            int s2 = st + STAGES - 1;
            if (s2 >= STAGES) s2 -= STAGES;
            fill_stage(s2, ls * BK);
        }

        if (++st == STAGES) st = 0;
    }

    // epilogue: scale by 1/len, store float2 pairs
    const float* lb = lens + b * Ndim;
    const int gid = lane >> 2, tq = lane & 3;
    #pragma unroll
    for (int i = 0; i < 4; i++) {
        const int r0 = m0 + wm * 64 + i * 16 + gid;
        const int r1 = r0 + 8;
        const float inv0 = 1.0f / lb[r0];
        const float inv1 = 1.0f / lb[r1];
        float* o0 = out + (size_t)b * Ndim * Hdim + (size_t)r0 * Hdim + h0;
        float* o1 = out + (size_t)b * Ndim * Hdim + (size_t)r1 * Hdim + h0;
        #pragma unroll
        for (int j = 0; j < 8; j++) {
            const int h = wn * 64 + j * 8 + 2 * tq;
            *reinterpret_cast<float2*>(o0 + h) =
                make_float2(acc[i][j][0] * inv0, acc[i][j][1] * inv0);
            *reinterpret_cast<float2*>(o1 + h) =
                make_float2(acc[i][j][2] * inv1, acc[i][j][3] * inv1);
        }
    }
}

extern "C" void kernel_launch(void* const* d_in, const int* in_sizes, int n_in,
                              void* d_out, int out_size) {
    const float* doc  = (const float*)d_in[0];   // [8, 4096, 1024]
    const float* map  = (const float*)d_in[1];   // [8, 512, 4096]
    const float* lens = (const float*)d_in[2];   // [8, 512]
    float* out = (float*)d_out;                  // [8, 512, 1024]

    cvt_all<<<CVT_BLOCKS, CVT_THREADS>>>(doc, map);

    cudaFuncSetAttribute(mean_pool_mma, cudaFuncAttributeMaxDynamicSharedMemorySize, DYN_SMEM);
    dim3 grid(Hdim / BN, Ndim / BM, Bdim);   // (8, 4, 8) = 256 CTAs
    mean_pool_mma<<<grid, NTHREADS, DYN_SMEM>>>(lens, out);
}